// round 4
// baseline (speedup 1.0000x reference)
#include <cuda_runtime.h>

#define N_NODES 100000
#define DIM 128
#define NCLS 40
#define E_CAP 1600000
#define SCAN_ELEMS 1024
#define SCAN_BLOCKS ((N_NODES + SCAN_ELEMS - 1) / SCAN_ELEMS)   // 98

// ---------------- scratch (device globals — no allocation allowed) ----------
__device__ float g_agg[(size_t)N_NODES * DIM];    // mean-aggregated x
__device__ float g_h[(size_t)N_NODES * DIM];      // hidden activations
__device__ float g_q[(size_t)N_NODES * NCLS];     // h @ W2_l (pre-aggregation)
__device__ float g_r[(size_t)N_NODES * NCLS];     // h @ W2_r (root term)
__device__ float g_inv_deg[N_NODES];
__device__ int   g_deg[N_NODES];
__device__ int   g_fill[N_NODES];
__device__ int   g_row_ptr[N_NODES + 1];
__device__ int   g_col[E_CAP];
__device__ int   g_bsum[SCAN_BLOCKS];
__device__ int   g_boff[SCAN_BLOCKS];
__device__ int   g_is64;

// ---------------- f32x2 helpers ----------------------------------------------
typedef unsigned long long ull;

__device__ __forceinline__ ull pk2(float lo, float hi) {
    ull r; asm("mov.b64 %0, {%1, %2};" : "=l"(r) : "f"(lo), "f"(hi)); return r;
}
__device__ __forceinline__ void upk2(ull v, float& lo, float& hi) {
    asm("mov.b64 {%0, %1}, %2;" : "=f"(lo), "=f"(hi) : "l"(v));
}
__device__ __forceinline__ ull fma2(ull a, ull b, ull c) {
    ull d; asm("fma.rn.f32x2 %0, %1, %2, %3;" : "=l"(d) : "l"(a), "l"(b), "l"(c)); return d;
}

__device__ __forceinline__ int load_idx(const int* ei32, size_t elem, int is64) {
    return is64 ? ei32[2 * elem] : ei32[elem];
}

// ---------------- init: zero counters + edge dtype detection -----------------
// edge_index is nominally int64, but JAX without x64 silently emits int32.
// int64 LE indices < 2^31 have zero high words at every odd int32 position.
__global__ void k_init(const int* __restrict__ ei32) {
    int i = blockIdx.x * blockDim.x + threadIdx.x;
    if (i < N_NODES) { g_deg[i] = 0; g_fill[i] = 0; }
    if (i == 0) {
        int is64 = 1;
        for (int j = 0; j < 64; j++)
            if (ei32[2 * j + 1] != 0) { is64 = 0; break; }
        g_is64 = is64;
    }
}

__global__ void k_hist(const int* __restrict__ ei32, int E) {
    int e = blockIdx.x * blockDim.x + threadIdx.x;
    if (e < E) {
        int d = load_idx(ei32, (size_t)E + e, g_is64);   // dst
        if (d >= 0 && d < N_NODES) atomicAdd(&g_deg[d], 1);
    }
}

// Phase 1: per-block exclusive scan of 1024 elements (256 thr x 4), block sums out.
__global__ void k_blockscan() {
    __shared__ int wsum[8];
    const int t = threadIdx.x;
    const int lane = t & 31, wid = t >> 5;
    const int base = blockIdx.x * SCAN_ELEMS + t * 4;

    int4 d = make_int4(0, 0, 0, 0);
    if (base + 3 < N_NODES) {
        d = *(const int4*)&g_deg[base];
    } else {
        int v[4] = {0, 0, 0, 0};
        for (int i = 0; i < 4; i++) if (base + i < N_NODES) v[i] = g_deg[base + i];
        d = make_int4(v[0], v[1], v[2], v[3]);
    }
    int s = d.x + d.y + d.z + d.w;

    int incl = s;
    #pragma unroll
    for (int off = 1; off < 32; off <<= 1) {
        int v = __shfl_up_sync(0xffffffffu, incl, off);
        if (lane >= off) incl += v;
    }
    if (lane == 31) wsum[wid] = incl;
    __syncthreads();
    if (wid == 0) {
        int v = (lane < 8) ? wsum[lane] : 0;
        #pragma unroll
        for (int off = 1; off < 8; off <<= 1) {
            int u = __shfl_up_sync(0xffffffffu, v, off);
            if (lane >= off) v += u;
        }
        if (lane < 8) wsum[lane] = v;
    }
    __syncthreads();

    int excl = incl - s + ((wid > 0) ? wsum[wid - 1] : 0);
    if (base < N_NODES) {
        int r0 = excl, r1 = r0 + d.x, r2 = r1 + d.y, r3 = r2 + d.z;
        if (base + 3 < N_NODES) {
            *(int4*)&g_row_ptr[base] = make_int4(r0, r1, r2, r3);
        } else {
            int r[4] = {r0, r1, r2, r3};
            for (int i = 0; i < 4; i++) if (base + i < N_NODES) g_row_ptr[base + i] = r[i];
        }
    }
    if (t == 255) g_bsum[blockIdx.x] = wsum[7];
}

// Phase 2: scan the 98 block sums.
__global__ void k_bsum_scan() {
    __shared__ int ws[4];
    const int t = threadIdx.x, lane = t & 31, wid = t >> 5;   // 128 threads
    int v = (t < SCAN_BLOCKS) ? g_bsum[t] : 0;
    int incl = v;
    #pragma unroll
    for (int off = 1; off < 32; off <<= 1) {
        int u = __shfl_up_sync(0xffffffffu, incl, off);
        if (lane >= off) incl += u;
    }
    if (lane == 31) ws[wid] = incl;
    __syncthreads();
    if (wid == 0) {
        int u = (lane < 4) ? ws[lane] : 0;
        #pragma unroll
        for (int off = 1; off < 4; off <<= 1) {
            int w = __shfl_up_sync(0xffffffffu, u, off);
            if (lane >= off) u += w;
        }
        if (lane < 4) ws[lane] = u;
    }
    __syncthreads();
    int excl = incl - v + ((wid > 0) ? ws[wid - 1] : 0);
    if (t < SCAN_BLOCKS) g_boff[t] = excl;
    if (t == 127) g_row_ptr[N_NODES] = ws[3];
}

// Phase 3: add block offsets; also compute inv_deg.
__global__ void k_addoff() {
    const int t = threadIdx.x;
    const int base = blockIdx.x * SCAN_ELEMS + t * 4;
    const int off = g_boff[blockIdx.x];
    #pragma unroll
    for (int i = 0; i < 4; i++) {
        int idx = base + i;
        if (idx < N_NODES) {
            g_row_ptr[idx] += off;
            int dg = g_deg[idx];
            g_inv_deg[idx] = 1.0f / (float)max(dg, 1);
        }
    }
}

__global__ void k_scatter(const int* __restrict__ ei32, int E) {
    int e = blockIdx.x * blockDim.x + threadIdx.x;
    if (e < E) {
        int is64 = g_is64;
        int d = load_idx(ei32, (size_t)E + e, is64);
        int s = load_idx(ei32, (size_t)e, is64);
        if (d >= 0 && d < N_NODES && s >= 0 && s < N_NODES) {
            int pos = g_row_ptr[d] + atomicAdd(&g_fill[d], 1);
            if (pos >= 0 && pos < E_CAP) g_col[pos] = s;
        }
    }
}

// ---------------- aggregation: warp per node, D=128 --------------------------
__global__ void k_agg128(const float* __restrict__ feat) {
    int gid = blockIdx.x * blockDim.x + threadIdx.x;
    int node = gid >> 5;
    if (node >= N_NODES) return;
    int lane = gid & 31;
    int beg = g_row_ptr[node], end = g_row_ptr[node + 1];

    float4 acc = make_float4(0.f, 0.f, 0.f, 0.f);
    int j = beg;
    for (; j + 4 <= end; j += 4) {
        int s0 = g_col[j], s1 = g_col[j + 1], s2 = g_col[j + 2], s3 = g_col[j + 3];
        float4 v0 = __ldg(((const float4*)(feat + (size_t)s0 * DIM)) + lane);
        float4 v1 = __ldg(((const float4*)(feat + (size_t)s1 * DIM)) + lane);
        float4 v2 = __ldg(((const float4*)(feat + (size_t)s2 * DIM)) + lane);
        float4 v3 = __ldg(((const float4*)(feat + (size_t)s3 * DIM)) + lane);
        acc.x += (v0.x + v1.x) + (v2.x + v3.x);
        acc.y += (v0.y + v1.y) + (v2.y + v3.y);
        acc.z += (v0.z + v1.z) + (v2.z + v3.z);
        acc.w += (v0.w + v1.w) + (v2.w + v3.w);
    }
    for (; j < end; j++) {
        int s0 = g_col[j];
        float4 v0 = __ldg(((const float4*)(feat + (size_t)s0 * DIM)) + lane);
        acc.x += v0.x; acc.y += v0.y; acc.z += v0.z; acc.w += v0.w;
    }
    float sc = g_inv_deg[node];
    acc.x *= sc; acc.y *= sc; acc.z *= sc; acc.w *= sc;
    *((float4*)(g_agg + (size_t)node * DIM) + lane) = acc;
}

// ---------------- layer 1: h = relu(agg@W1_l + x@W1_r + b1) -------------------
// 64 threads; tile 16 rows x 128 cols; thread = 4 rows x 8 cols.
// A/X duplicated in smem ({a,a} pairs) so one broadcast LDS.64 feeds
// fma.rn.f32x2. Row stride padded to 130 ull (1040B = 65*16B): 16B-aligned
// rows AND bank-shift 16 between rowgroups (no LDS conflicts).
#define L1_PAD 130
__global__ void k_layer1(const float* __restrict__ x,
                         const float* __restrict__ W1l,
                         const float* __restrict__ b1,
                         const float* __restrict__ W1r) {
    __shared__ ull sad[16][L1_PAD];
    __shared__ ull sxd[16][L1_PAD];
    const int row0 = blockIdx.x * 16;
    const int tid = threadIdx.x;

    // load + duplicate: 512 float4s per tile, 64 threads x 8
    {
        const float4* ga = (const float4*)(g_agg + (size_t)row0 * DIM);
        const float4* gx = (const float4*)(x + (size_t)row0 * DIM);
        #pragma unroll
        for (int i = 0; i < 8; i++) {
            int idx = tid + i * 64;            // float4 linear index
            int row = idx >> 5;                // 32 float4 per row
            int c = (idx & 31) * 4;            // starting k
            float4 va = ga[idx];
            float4 vx = gx[idx];
            float4* da = (float4*)&sad[row][c];
            da[0] = make_float4(va.x, va.x, va.y, va.y);
            da[1] = make_float4(va.z, va.z, va.w, va.w);
            float4* dx = (float4*)&sxd[row][c];
            dx[0] = make_float4(vx.x, vx.x, vx.y, vx.y);
            dx[1] = make_float4(vx.z, vx.z, vx.w, vx.w);
        }
    }
    __syncthreads();

    const int c0 = (tid & 15) * 8;   // 8 output columns
    const int r0 = (tid >> 4) * 4;   // 4 rows

    ull acc[4][4];
    {
        float4 bb0 = __ldg((const float4*)(b1 + c0));
        float4 bb1 = __ldg((const float4*)(b1 + c0 + 4));
        ull p0 = pk2(bb0.x, bb0.y), p1 = pk2(bb0.z, bb0.w);
        ull p2 = pk2(bb1.x, bb1.y), p3 = pk2(bb1.z, bb1.w);
        #pragma unroll
        for (int ri = 0; ri < 4; ri++) {
            acc[ri][0] = p0; acc[ri][1] = p1; acc[ri][2] = p2; acc[ri][3] = p3;
        }
    }

    #pragma unroll 2
    for (int k = 0; k < DIM; k++) {
        ulonglong2 wl0 = __ldg((const ulonglong2*)(W1l + (size_t)k * DIM + c0));
        ulonglong2 wl1 = __ldg((const ulonglong2*)(W1l + (size_t)k * DIM + c0 + 4));
        ulonglong2 wr0 = __ldg((const ulonglong2*)(W1r + (size_t)k * DIM + c0));
        ulonglong2 wr1 = __ldg((const ulonglong2*)(W1r + (size_t)k * DIM + c0 + 4));
        #pragma unroll
        for (int ri = 0; ri < 4; ri++) {
            ull a  = sad[r0 + ri][k];
            ull xv = sxd[r0 + ri][k];
            acc[ri][0] = fma2(a,  wl0.x, acc[ri][0]);
            acc[ri][1] = fma2(a,  wl0.y, acc[ri][1]);
            acc[ri][2] = fma2(a,  wl1.x, acc[ri][2]);
            acc[ri][3] = fma2(a,  wl1.y, acc[ri][3]);
            acc[ri][0] = fma2(xv, wr0.x, acc[ri][0]);
            acc[ri][1] = fma2(xv, wr0.y, acc[ri][1]);
            acc[ri][2] = fma2(xv, wr1.x, acc[ri][2]);
            acc[ri][3] = fma2(xv, wr1.y, acc[ri][3]);
        }
    }

    #pragma unroll
    for (int ri = 0; ri < 4; ri++) {
        float o0, o1, o2, o3, o4, o5, o6, o7;
        upk2(acc[ri][0], o0, o1);
        upk2(acc[ri][1], o2, o3);
        upk2(acc[ri][2], o4, o5);
        upk2(acc[ri][3], o6, o7);
        float* hp = g_h + (size_t)(row0 + r0 + ri) * DIM + c0;
        *((float4*)hp)     = make_float4(fmaxf(o0,0.f), fmaxf(o1,0.f), fmaxf(o2,0.f), fmaxf(o3,0.f));
        *((float4*)hp + 1) = make_float4(fmaxf(o4,0.f), fmaxf(o5,0.f), fmaxf(o6,0.f), fmaxf(o7,0.f));
    }
}

// ---------------- layer 2: q = h@W2_l, r = h@W2_r (f32x2 packed) --------------
// 320 threads; tile 32 rows. unit = tid%40: units 0..19 -> W2_l col pair,
// 20..39 -> W2_r col pair. rowgroup = tid/40 (0..7), 4 rows each.
#define L2_PAD 130
__global__ void k_layer2(const float* __restrict__ W2l,
                         const float* __restrict__ W2r) {
    __shared__ ull shd[32][L2_PAD];   // shd[row][k] = {h, h}
    const int row0 = blockIdx.x * 32;
    const int t = threadIdx.x;

    {
        const float4* gh = (const float4*)(g_h + (size_t)row0 * DIM);
        for (int i = t; i < 1024; i += 320) {
            int row = i >> 5;
            int c = (i & 31) * 4;
            float4 v = gh[i];
            float4* dd = (float4*)&shd[row][c];
            dd[0] = make_float4(v.x, v.x, v.y, v.y);
            dd[1] = make_float4(v.z, v.z, v.w, v.w);
        }
    }
    __syncthreads();

    const int unit = t % 40;
    const int r0 = (t / 40) * 4;
    const bool is_l = (unit < 20);
    const int c0 = (is_l ? unit : unit - 20) * 2;
    const float* W = is_l ? W2l : W2r;

    ull acc0 = 0, acc1 = 0, acc2 = 0, acc3 = 0;
    #pragma unroll 4
    for (int k = 0; k < DIM; k++) {
        ull w = __ldg((const ull*)(W + (size_t)k * NCLS + c0));
        acc0 = fma2(shd[r0 + 0][k], w, acc0);
        acc1 = fma2(shd[r0 + 1][k], w, acc1);
        acc2 = fma2(shd[r0 + 2][k], w, acc2);
        acc3 = fma2(shd[r0 + 3][k], w, acc3);
    }
    float* outp = is_l ? g_q : g_r;
    *(ull*)&outp[(size_t)(row0 + r0 + 0) * NCLS + c0] = acc0;
    *(ull*)&outp[(size_t)(row0 + r0 + 1) * NCLS + c0] = acc1;
    *(ull*)&outp[(size_t)(row0 + r0 + 2) * NCLS + c0] = acc2;
    *(ull*)&outp[(size_t)(row0 + r0 + 3) * NCLS + c0] = acc3;
}

// ---------------- fused: agg(q) + root + bias + log_softmax -------------------
__global__ void k_final(const float* __restrict__ b2, float* __restrict__ out) {
    int gid = blockIdx.x * blockDim.x + threadIdx.x;
    int node = gid >> 5;
    if (node >= N_NODES) return;
    int lane = gid & 31;
    int beg = g_row_ptr[node], end = g_row_ptr[node + 1];

    float acc0 = 0.f, acc1 = 0.f;
    int j = beg;
    for (; j + 2 <= end; j += 2) {
        int s0 = g_col[j], s1 = g_col[j + 1];
        const float* q0 = g_q + (size_t)s0 * NCLS;
        const float* q1 = g_q + (size_t)s1 * NCLS;
        acc0 += __ldg(q0 + lane) + __ldg(q1 + lane);
        if (lane < 8) acc1 += __ldg(q0 + 32 + lane) + __ldg(q1 + 32 + lane);
    }
    if (j < end) {
        const float* q0 = g_q + (size_t)g_col[j] * NCLS;
        acc0 += __ldg(q0 + lane);
        if (lane < 8) acc1 += __ldg(q0 + 32 + lane);
    }

    float sc = g_inv_deg[node];
    const size_t base = (size_t)node * NCLS;
    float va = acc0 * sc + g_r[base + lane] + __ldg(b2 + lane);
    float vb = -1e30f;
    if (lane < 8)
        vb = acc1 * sc + g_r[base + 32 + lane] + __ldg(b2 + 32 + lane);

    float m = fmaxf(va, vb);
    #pragma unroll
    for (int off = 16; off > 0; off >>= 1)
        m = fmaxf(m, __shfl_xor_sync(0xffffffffu, m, off));

    float s = expf(va - m) + ((lane < 8) ? expf(vb - m) : 0.f);
    #pragma unroll
    for (int off = 16; off > 0; off >>= 1)
        s += __shfl_xor_sync(0xffffffffu, s, off);

    float lse = m + logf(s);
    out[base + lane] = va - lse;
    if (lane < 8) out[base + 32 + lane] = vb - lse;
}

// ---------------- launch -----------------------------------------------------
extern "C" void kernel_launch(void* const* d_in, const int* in_sizes, int n_in,
                              void* d_out, int out_size) {
    const float* x   = (const float*)d_in[0];
    const int*   ei  = (const int*)d_in[1];       // int32 OR int64 (detected)
    const float* W1l = (const float*)d_in[2];
    const float* b1  = (const float*)d_in[3];
    const float* W1r = (const float*)d_in[4];
    const float* W2l = (const float*)d_in[5];
    const float* b2  = (const float*)d_in[6];
    const float* W2r = (const float*)d_in[7];
    float* out = (float*)d_out;

    const int E = in_sizes[1] / 2;

    k_init<<<(N_NODES + 255) / 256, 256>>>(ei);
    k_hist<<<(E + 255) / 256, 256>>>(ei, E);
    k_blockscan<<<SCAN_BLOCKS, 256>>>();
    k_bsum_scan<<<1, 128>>>();
    k_addoff<<<SCAN_BLOCKS, 256>>>();
    k_scatter<<<(E + 255) / 256, 256>>>(ei, E);

    const int agg_blocks = (N_NODES * 32 + 255) / 256;
    k_agg128<<<agg_blocks, 256>>>(x);
    k_layer1<<<N_NODES / 16, 64>>>(x, W1l, b1, W1r);
    k_layer2<<<N_NODES / 32, 320>>>(W2l, W2r);
    k_final<<<agg_blocks, 256>>>(b2, out);
}

// round 5
// speedup vs baseline: 1.3616x; 1.3616x over previous
#include <cuda_runtime.h>

#define N_NODES 100000
#define DIM 128
#define NCLS 40
#define E_CAP 1600000
#define SCAN_ELEMS 1024
#define SCAN_BLOCKS ((N_NODES + SCAN_ELEMS - 1) / SCAN_ELEMS)   // 98

// ---------------- scratch (device globals — no allocation allowed) ----------
__device__ float g_agg[(size_t)N_NODES * DIM];    // mean-aggregated x
__device__ float g_h[(size_t)N_NODES * DIM];      // hidden activations
__device__ float g_q[(size_t)N_NODES * NCLS];     // h @ W2_l (pre-aggregation)
__device__ float g_r[(size_t)N_NODES * NCLS];     // h @ W2_r (root term)
__device__ float g_inv_deg[N_NODES];
__device__ int   g_deg[N_NODES];
__device__ int   g_fill[N_NODES];
__device__ int   g_row_ptr[N_NODES + 1];
__device__ int   g_col[E_CAP];
__device__ int   g_bsum[SCAN_BLOCKS];
__device__ int   g_boff[SCAN_BLOCKS];
__device__ int   g_is64;

// ---------------- f32x2 helpers ----------------------------------------------
typedef unsigned long long ull;

__device__ __forceinline__ ull pk2(float lo, float hi) {
    ull r; asm("mov.b64 %0, {%1, %2};" : "=l"(r) : "f"(lo), "f"(hi)); return r;
}
__device__ __forceinline__ void upk2(ull v, float& lo, float& hi) {
    asm("mov.b64 {%0, %1}, %2;" : "=f"(lo), "=f"(hi) : "l"(v));
}
__device__ __forceinline__ ull fma2(ull a, ull b, ull c) {
    ull d; asm("fma.rn.f32x2 %0, %1, %2, %3;" : "=l"(d) : "l"(a), "l"(b), "l"(c)); return d;
}

__device__ __forceinline__ int load_idx(const int* ei32, size_t elem, int is64) {
    return is64 ? ei32[2 * elem] : ei32[elem];
}

// ---------------- init: zero counters + edge dtype detection -----------------
// edge_index is nominally int64, but JAX without x64 silently emits int32.
// int64 LE indices < 2^31 have zero high words at every odd int32 position.
__global__ void k_init(const int* __restrict__ ei32) {
    int i = blockIdx.x * blockDim.x + threadIdx.x;
    if (i < N_NODES) { g_deg[i] = 0; g_fill[i] = 0; }
    if (i == 0) {
        int is64 = 1;
        for (int j = 0; j < 64; j++)
            if (ei32[2 * j + 1] != 0) { is64 = 0; break; }
        g_is64 = is64;
    }
}

__global__ void k_hist(const int* __restrict__ ei32, int E) {
    int e = blockIdx.x * blockDim.x + threadIdx.x;
    if (e < E) {
        int d = load_idx(ei32, (size_t)E + e, g_is64);   // dst
        if (d >= 0 && d < N_NODES) atomicAdd(&g_deg[d], 1);
    }
}

// Phase 1: per-block exclusive scan of 1024 elements (256 thr x 4), block sums out.
__global__ void k_blockscan() {
    __shared__ int wsum[8];
    const int t = threadIdx.x;
    const int lane = t & 31, wid = t >> 5;
    const int base = blockIdx.x * SCAN_ELEMS + t * 4;

    int4 d = make_int4(0, 0, 0, 0);
    if (base + 3 < N_NODES) {
        d = *(const int4*)&g_deg[base];
    } else {
        int v[4] = {0, 0, 0, 0};
        for (int i = 0; i < 4; i++) if (base + i < N_NODES) v[i] = g_deg[base + i];
        d = make_int4(v[0], v[1], v[2], v[3]);
    }
    int s = d.x + d.y + d.z + d.w;

    int incl = s;
    #pragma unroll
    for (int off = 1; off < 32; off <<= 1) {
        int v = __shfl_up_sync(0xffffffffu, incl, off);
        if (lane >= off) incl += v;
    }
    if (lane == 31) wsum[wid] = incl;
    __syncthreads();
    if (wid == 0) {
        int v = (lane < 8) ? wsum[lane] : 0;
        #pragma unroll
        for (int off = 1; off < 8; off <<= 1) {
            int u = __shfl_up_sync(0xffffffffu, v, off);
            if (lane >= off) v += u;
        }
        if (lane < 8) wsum[lane] = v;
    }
    __syncthreads();

    int excl = incl - s + ((wid > 0) ? wsum[wid - 1] : 0);
    if (base < N_NODES) {
        int r0 = excl, r1 = r0 + d.x, r2 = r1 + d.y, r3 = r2 + d.z;
        if (base + 3 < N_NODES) {
            *(int4*)&g_row_ptr[base] = make_int4(r0, r1, r2, r3);
        } else {
            int r[4] = {r0, r1, r2, r3};
            for (int i = 0; i < 4; i++) if (base + i < N_NODES) g_row_ptr[base + i] = r[i];
        }
    }
    if (t == 255) g_bsum[blockIdx.x] = wsum[7];
}

// Phase 2: scan the 98 block sums.
__global__ void k_bsum_scan() {
    __shared__ int ws[4];
    const int t = threadIdx.x, lane = t & 31, wid = t >> 5;   // 128 threads
    int v = (t < SCAN_BLOCKS) ? g_bsum[t] : 0;
    int incl = v;
    #pragma unroll
    for (int off = 1; off < 32; off <<= 1) {
        int u = __shfl_up_sync(0xffffffffu, incl, off);
        if (lane >= off) incl += u;
    }
    if (lane == 31) ws[wid] = incl;
    __syncthreads();
    if (wid == 0) {
        int u = (lane < 4) ? ws[lane] : 0;
        #pragma unroll
        for (int off = 1; off < 4; off <<= 1) {
            int w = __shfl_up_sync(0xffffffffu, u, off);
            if (lane >= off) u += w;
        }
        if (lane < 4) ws[lane] = u;
    }
    __syncthreads();
    int excl = incl - v + ((wid > 0) ? ws[wid - 1] : 0);
    if (t < SCAN_BLOCKS) g_boff[t] = excl;
    if (t == 127) g_row_ptr[N_NODES] = ws[3];
}

// Phase 3: add block offsets; also compute inv_deg.
__global__ void k_addoff() {
    const int t = threadIdx.x;
    const int base = blockIdx.x * SCAN_ELEMS + t * 4;
    const int off = g_boff[blockIdx.x];
    #pragma unroll
    for (int i = 0; i < 4; i++) {
        int idx = base + i;
        if (idx < N_NODES) {
            g_row_ptr[idx] += off;
            int dg = g_deg[idx];
            g_inv_deg[idx] = 1.0f / (float)max(dg, 1);
        }
    }
}

__global__ void k_scatter(const int* __restrict__ ei32, int E) {
    int e = blockIdx.x * blockDim.x + threadIdx.x;
    if (e < E) {
        int is64 = g_is64;
        int d = load_idx(ei32, (size_t)E + e, is64);
        int s = load_idx(ei32, (size_t)e, is64);
        if (d >= 0 && d < N_NODES && s >= 0 && s < N_NODES) {
            int pos = g_row_ptr[d] + atomicAdd(&g_fill[d], 1);
            if (pos >= 0 && pos < E_CAP) g_col[pos] = s;
        }
    }
}

// ---------------- aggregation: warp per node, D=128 --------------------------
__global__ void k_agg128(const float* __restrict__ feat) {
    int gid = blockIdx.x * blockDim.x + threadIdx.x;
    int node = gid >> 5;
    if (node >= N_NODES) return;
    int lane = gid & 31;
    int beg = g_row_ptr[node], end = g_row_ptr[node + 1];

    float4 acc = make_float4(0.f, 0.f, 0.f, 0.f);
    int j = beg;
    for (; j + 2 <= end; j += 2) {
        int s0 = g_col[j], s1 = g_col[j + 1];
        float4 v0 = __ldg(((const float4*)(feat + (size_t)s0 * DIM)) + lane);
        float4 v1 = __ldg(((const float4*)(feat + (size_t)s1 * DIM)) + lane);
        acc.x += v0.x + v1.x; acc.y += v0.y + v1.y;
        acc.z += v0.z + v1.z; acc.w += v0.w + v1.w;
    }
    if (j < end) {
        int s0 = g_col[j];
        float4 v0 = __ldg(((const float4*)(feat + (size_t)s0 * DIM)) + lane);
        acc.x += v0.x; acc.y += v0.y; acc.z += v0.z; acc.w += v0.w;
    }
    float sc = g_inv_deg[node];
    acc.x *= sc; acc.y *= sc; acc.z *= sc; acc.w *= sc;
    *((float4*)(g_agg + (size_t)node * DIM) + lane) = acc;
}

// ---------------- layer 1: h = relu(agg@W1_l + x@W1_r + b1) -------------------
// (round-3 measured-good config) 128 threads, tile 16x128, thread = 4x4,
// duplicated smem {a,a} feeding fma.rn.f32x2.
__global__ void k_layer1(const float* __restrict__ x,
                         const float* __restrict__ W1l,
                         const float* __restrict__ b1,
                         const float* __restrict__ W1r) {
    __shared__ ull sad[16][DIM];   // sad[row][k] = {a, a}
    __shared__ ull sxd[16][DIM];   // sxd[row][k] = {x, x}
    const int row0 = blockIdx.x * 16;
    const int tid = threadIdx.x;

    {
        const float4* ga = (const float4*)(g_agg + (size_t)row0 * DIM);
        const float4* gx = (const float4*)(x + (size_t)row0 * DIM);
        #pragma unroll
        for (int i = 0; i < 4; i++) {
            int idx = tid + i * 128;
            int row = idx >> 5;
            int c = (idx & 31) * 4;
            float4 va = ga[idx];
            float4 vx = gx[idx];
            float4* da = (float4*)&sad[row][c];
            da[0] = make_float4(va.x, va.x, va.y, va.y);
            da[1] = make_float4(va.z, va.z, va.w, va.w);
            float4* dx = (float4*)&sxd[row][c];
            dx[0] = make_float4(vx.x, vx.x, vx.y, vx.y);
            dx[1] = make_float4(vx.z, vx.z, vx.w, vx.w);
        }
    }
    __syncthreads();

    const int c0 = (tid & 31) * 4;
    const int rb = (tid >> 5) * 4;

    ull acc[4][2];
    {
        float4 bb = __ldg((const float4*)(b1 + c0));
        ull b01 = pk2(bb.x, bb.y), b23 = pk2(bb.z, bb.w);
        #pragma unroll
        for (int ri = 0; ri < 4; ri++) { acc[ri][0] = b01; acc[ri][1] = b23; }
    }

    #pragma unroll 4
    for (int k = 0; k < DIM; k++) {
        ulonglong2 wl = __ldg((const ulonglong2*)(W1l + (size_t)k * DIM + c0));
        ulonglong2 wr = __ldg((const ulonglong2*)(W1r + (size_t)k * DIM + c0));
        #pragma unroll
        for (int ri = 0; ri < 4; ri++) {
            ull a  = sad[rb + ri][k];
            ull xv = sxd[rb + ri][k];
            acc[ri][0] = fma2(a,  wl.x, acc[ri][0]);
            acc[ri][1] = fma2(a,  wl.y, acc[ri][1]);
            acc[ri][0] = fma2(xv, wr.x, acc[ri][0]);
            acc[ri][1] = fma2(xv, wr.y, acc[ri][1]);
        }
    }

    #pragma unroll
    for (int ri = 0; ri < 4; ri++) {
        float o0, o1, o2, o3;
        upk2(acc[ri][0], o0, o1);
        upk2(acc[ri][1], o2, o3);
        float4 o;
        o.x = fmaxf(o0, 0.f); o.y = fmaxf(o1, 0.f);
        o.z = fmaxf(o2, 0.f); o.w = fmaxf(o3, 0.f);
        *((float4*)(g_h + (size_t)(row0 + rb + ri) * DIM + c0)) = o;
    }
}

// ---------------- layer 2 projections: q = h@W2_l, r = h@W2_r -----------------
// (round-3 measured-good config) 320 threads, 16-row tile, scalar FFMA.
__global__ void k_layer2(const float* __restrict__ W2l,
                         const float* __restrict__ W2r) {
    __shared__ float sh[16][DIM];
    const int row0 = blockIdx.x * 16;
    const int t = threadIdx.x;

    {
        const float4* gh = (const float4*)(g_h + (size_t)row0 * DIM);
        float4* ls = (float4*)&sh[0][0];
        for (int i = t; i < 512; i += 320) ls[i] = gh[i];
    }
    __syncthreads();

    const int oc = t % 80;
    const int rg = (t / 80) * 4;
    const bool is_l = (oc < NCLS);
    const int c = is_l ? oc : oc - NCLS;
    const float* W = is_l ? W2l : W2r;

    float a0 = 0.f, a1 = 0.f, a2 = 0.f, a3 = 0.f;
    #pragma unroll 8
    for (int k = 0; k < DIM; k++) {
        float w = __ldg(W + (size_t)k * NCLS + c);
        a0 += sh[rg + 0][k] * w;
        a1 += sh[rg + 1][k] * w;
        a2 += sh[rg + 2][k] * w;
        a3 += sh[rg + 3][k] * w;
    }
    float* outp = is_l ? g_q : g_r;
    outp[(size_t)(row0 + rg + 0) * NCLS + c] = a0;
    outp[(size_t)(row0 + rg + 1) * NCLS + c] = a1;
    outp[(size_t)(row0 + rg + 2) * NCLS + c] = a2;
    outp[(size_t)(row0 + rg + 3) * NCLS + c] = a3;
}

// ---------------- fused: agg(q) + root + bias + log_softmax -------------------
__global__ void k_final(const float* __restrict__ b2, float* __restrict__ out) {
    int gid = blockIdx.x * blockDim.x + threadIdx.x;
    int node = gid >> 5;
    if (node >= N_NODES) return;
    int lane = gid & 31;
    int beg = g_row_ptr[node], end = g_row_ptr[node + 1];

    float acc0 = 0.f, acc1 = 0.f;
    int j = beg;
    for (; j + 2 <= end; j += 2) {
        int s0 = g_col[j], s1 = g_col[j + 1];
        const float* q0 = g_q + (size_t)s0 * NCLS;
        const float* q1 = g_q + (size_t)s1 * NCLS;
        acc0 += __ldg(q0 + lane) + __ldg(q1 + lane);
        if (lane < 8) acc1 += __ldg(q0 + 32 + lane) + __ldg(q1 + 32 + lane);
    }
    if (j < end) {
        const float* q0 = g_q + (size_t)g_col[j] * NCLS;
        acc0 += __ldg(q0 + lane);
        if (lane < 8) acc1 += __ldg(q0 + 32 + lane);
    }

    float sc = g_inv_deg[node];
    const size_t base = (size_t)node * NCLS;
    float va = acc0 * sc + g_r[base + lane] + __ldg(b2 + lane);
    float vb = -1e30f;
    if (lane < 8)
        vb = acc1 * sc + g_r[base + 32 + lane] + __ldg(b2 + 32 + lane);

    float m = fmaxf(va, vb);
    #pragma unroll
    for (int off = 16; off > 0; off >>= 1)
        m = fmaxf(m, __shfl_xor_sync(0xffffffffu, m, off));

    float s = expf(va - m) + ((lane < 8) ? expf(vb - m) : 0.f);
    #pragma unroll
    for (int off = 16; off > 0; off >>= 1)
        s += __shfl_xor_sync(0xffffffffu, s, off);

    float lse = m + logf(s);
    out[base + lane] = va - lse;
    if (lane < 8) out[base + 32 + lane] = vb - lse;
}

// ---------------- launch -----------------------------------------------------
extern "C" void kernel_launch(void* const* d_in, const int* in_sizes, int n_in,
                              void* d_out, int out_size) {
    const float* x   = (const float*)d_in[0];
    const int*   ei  = (const int*)d_in[1];       // int32 OR int64 (detected)
    const float* W1l = (const float*)d_in[2];
    const float* b1  = (const float*)d_in[3];
    const float* W1r = (const float*)d_in[4];
    const float* W2l = (const float*)d_in[5];
    const float* b2  = (const float*)d_in[6];
    const float* W2r = (const float*)d_in[7];
    float* out = (float*)d_out;

    const int E = in_sizes[1] / 2;

    k_init<<<(N_NODES + 255) / 256, 256>>>(ei);
    k_hist<<<(E + 255) / 256, 256>>>(ei, E);
    k_blockscan<<<SCAN_BLOCKS, 256>>>();
    k_bsum_scan<<<1, 128>>>();
    k_addoff<<<SCAN_BLOCKS, 256>>>();
    k_scatter<<<(E + 255) / 256, 256>>>(ei, E);

    const int agg_blocks = (N_NODES * 32 + 255) / 256;
    k_agg128<<<agg_blocks, 256>>>(x);
    k_layer1<<<N_NODES / 16, 128>>>(x, W1l, b1, W1r);
    k_layer2<<<N_NODES / 16, 320>>>(W2l, W2r);
    k_final<<<agg_blocks, 256>>>(b2, out);
}